// round 2
// baseline (speedup 1.0000x reference)
#include <cuda_runtime.h>

// Problem geometry: (B, D, H, W) = (2, 192, 192, 192) fp32
#define BB 2
#define DD 192
#define HH 192
#define WW 192
#define NELEM 14155776          // 2*192*192*192
#define PLANE 36864             // H*W

// Scratch: ping-pong, 3 fields each (t_sum, p_sum, tp_sum). Static device
// globals -> no allocation in kernel_launch (harness rule).
__device__ float g_A0[NELEM];
__device__ float g_A1[NELEM];
__device__ float g_A2[NELEM];
__device__ float g_B0[NELEM];
__device__ float g_B1[NELEM];
__device__ float g_B2[NELEM];

// ---------------------------------------------------------------------------
// Pass 1: box-9 sum along W (contiguous). One block per row, exact 9-tap via
// shared memory with zero pads (SAME zero padding).
// ---------------------------------------------------------------------------
__global__ void __launch_bounds__(192) pass1_kernel(const float* __restrict__ t,
                                                    const float* __restrict__ p) {
    __shared__ float st[200];
    __shared__ float sp[200];
    const int i = threadIdx.x;            // 0..191
    const int base = blockIdx.x * WW;     // row base, fits int (max ~14.1M)

    if (i < 4) {
        st[i] = 0.f;       sp[i] = 0.f;
        st[196 + i] = 0.f; sp[196 + i] = 0.f;
    }
    const float tv = t[base + i];
    const float pv = p[base + i];
    st[i + 4] = tv;
    sp[i + 4] = pv;
    __syncthreads();

    float s_t = 0.f, s_p = 0.f, s_tp = 0.f;
#pragma unroll
    for (int k = 0; k < 9; ++k) {
        const float a = st[i + k];
        const float c = sp[i + k];
        s_t += a;
        s_p += c;
        s_tp = fmaf(a, c, s_tp);
    }
    g_A0[base + i] = s_t;
    g_A1[base + i] = s_p;
    g_A2[base + i] = s_tp;
}

// ---------------------------------------------------------------------------
// Pass 2: box-9 sum along H (stride W). Block = one (b,d) slab half; thread
// per w; sliding window add/sub (the h-4 reload is an L1 hit).
// ---------------------------------------------------------------------------
__global__ void __launch_bounds__(192) pass2_kernel() {
    const int w     = threadIdx.x;
    const int chunk = blockIdx.x & 1;      // h-chunk: [0,96) or [96,192)
    const int bd    = blockIdx.x >> 1;     // 0..383 = b*192 + d
    const int h0    = chunk * 96;
    const int base  = bd * PLANE + w;

    float s0 = 0.f, s1 = 0.f, s2 = 0.f;
#pragma unroll
    for (int k = 0; k < 9; ++k) {
        const int j = h0 - 4 + k;
        if (j >= 0 && j < HH) {
            const int idx = base + j * WW;
            s0 += g_A0[idx];
            s1 += g_A1[idx];
            s2 += g_A2[idx];
        }
    }
    for (int h = h0; h < h0 + 96; ++h) {
        const int idx = base + h * WW;
        g_B0[idx] = s0;
        g_B1[idx] = s1;
        g_B2[idx] = s2;
        const int ja = h + 5;
        const int jr = h - 4;
        if (ja < HH) {
            const int ia = base + ja * WW;
            s0 += g_A0[ia];
            s1 += g_A1[ia];
            s2 += g_A2[ia];
        }
        if (jr >= 0) {
            const int ir = base + jr * WW;
            s0 -= g_A0[ir];
            s1 -= g_A1[ir];
            s2 -= g_A2[ir];
        }
    }
}

// ---------------------------------------------------------------------------
// Pass 3: box-9 sum along D (stride H*W) fused with the LNCC epilogue:
//   cross = tp_sum - p_sum * t_sum / 729 ; out = cross^2 + 1e-5
// Block = one b x 256-wide (h,w) tile x d-chunk; sliding along d.
// ---------------------------------------------------------------------------
__global__ void __launch_bounds__(256) pass3_kernel(float* __restrict__ out) {
    const int chunk = blockIdx.x & 1;          // d-chunk: [0,96) or [96,192)
    const int rest  = blockIdx.x >> 1;
    const int tile  = rest % 144;              // 144 tiles of 256 -> 36864
    const int b     = rest / 144;
    const int hw    = tile * 256 + threadIdx.x;
    const int d0    = chunk * 96;
    const int base  = b * (DD * PLANE) + hw;   // max ~7.1M, fits int

    float s0 = 0.f, s1 = 0.f, s2 = 0.f;
#pragma unroll
    for (int k = 0; k < 9; ++k) {
        const int j = d0 - 4 + k;
        if (j >= 0 && j < DD) {
            const int idx = base + j * PLANE;
            s0 += g_B0[idx];
            s1 += g_B1[idx];
            s2 += g_B2[idx];
        }
    }
    const float inv_vol = 1.0f / 729.0f;
    for (int d = d0; d < d0 + 96; ++d) {
        const int idx = base + d * PLANE;
        const float cross = s2 - s1 * s0 * inv_vol;
        out[idx] = fmaf(cross, cross, 1e-5f);
        const int ja = d + 5;
        const int jr = d - 4;
        if (ja < DD) {
            const int ia = base + ja * PLANE;
            s0 += g_B0[ia];
            s1 += g_B1[ia];
            s2 += g_B2[ia];
        }
        if (jr >= 0) {
            const int ir = base + jr * PLANE;
            s0 -= g_B0[ir];
            s1 -= g_B1[ir];
            s2 -= g_B2[ir];
        }
    }
}

// ---------------------------------------------------------------------------
extern "C" void kernel_launch(void* const* d_in, const int* in_sizes, int n_in,
                              void* d_out, int out_size) {
    const float* y_true = (const float*)d_in[0];
    const float* y_pred = (const float*)d_in[1];
    float* out = (float*)d_out;

    pass1_kernel<<<BB * DD * HH, 192>>>(y_true, y_pred);   // 73728 blocks
    pass2_kernel<<<BB * DD * 2, 192>>>();                  // 768 blocks
    pass3_kernel<<<BB * 144 * 2, 256>>>(out);              // 576 blocks
}

// round 3
// speedup vs baseline: 2.3668x; 2.3668x over previous
#include <cuda_runtime.h>

// (B, D, H, W) = (2, 192, 192, 192) fp32
#define BB 2
#define DD 192
#define HH 192
#define WW 192
#define PLANE 36864        // H*W
#define VOL   7077888      // D*H*W

#define TILE   32          // output tile in h and w
#define INROWS 40          // TILE + 8 halo
#define INCOLS 40
#define INSTR  41          // padded float2 stride for input tile
#define SWSTR  33          // padded stride for W-sum arrays
#define DCHUNK 48          // d-extent per block
#define NT     512         // threads per block

#define INV_VOL (1.0f / 729.0f)
#define EPS 1e-5f

// Fully fused 9^3 box-sum LNCC:
//   pass over d with an 8-deep register ring of HW-box-sums per output pixel.
//   Per d-slice: stage (40x40) input tile in smem (double buffered, prefetched),
//   W-sums via per-thread 4-wide sliding window, H-sums via 10-row reads with
//   2 h-outputs per thread, then ring add/sub along d + fused epilogue.
__global__ void __launch_bounds__(NT, 1)
lncc_fused_kernel(const float* __restrict__ gt,
                  const float* __restrict__ gp,
                  float* __restrict__ out)
{
    __shared__ float2 s_in[2][INROWS][INSTR];   // (t,p) interleaved, 26.2 KB
    __shared__ float2 s_w01[INROWS][SWSTR];     // (sum_t, sum_p)      10.6 KB
    __shared__ float  s_w2 [INROWS][SWSTR];     // sum_tp               5.3 KB

    const int tid = threadIdx.x;
    const int bx  = blockIdx.x;
    const int wt  = bx % 6;
    const int ht  = (bx / 6) % 6;
    const int dc  = (bx / 36) % 4;
    const int b   = bx / 144;

    const int w0 = wt * TILE;
    const int h0 = ht * TILE;
    const int d0 = dc * DCHUNK;

    // ---- per-thread register staging for one prefetched input slice ----
    float rt[4], rp[4];

    auto load_slice = [&](int dz) {
        const bool dok = (unsigned)dz < DD;
        const int dbase = b * VOL + dz * PLANE;
#pragma unroll
        for (int k = 0; k < 4; ++k) {
            const int i = tid + k * NT;
            float tv = 0.f, pv = 0.f;
            if (i < INROWS * INCOLS) {
                const int r  = i / INCOLS;
                const int c  = i - r * INCOLS;
                const int gh = h0 - 4 + r;
                const int gw = w0 - 4 + c;
                if (dok && (unsigned)gh < HH && (unsigned)gw < WW) {
                    const int a = dbase + gh * WW + gw;
                    tv = gt[a];
                    pv = gp[a];
                }
            }
            rt[k] = tv; rp[k] = pv;
        }
    };

    auto store_slice = [&](int bsel) {
#pragma unroll
        for (int k = 0; k < 4; ++k) {
            const int i = tid + k * NT;
            if (i < INROWS * INCOLS) {
                const int r = i / INCOLS;
                const int c = i - r * INCOLS;
                s_in[bsel][r][c] = make_float2(rt[k], rp[k]);
            }
        }
    };

    // W-stage: 320 tasks = 40 rows x 8 segments of 4 outputs (sliding window)
    auto w_stage = [&](int bsel) {
        if (tid < 320) {
            const int r  = tid >> 3;
            const int j0 = (tid & 7) << 2;
            const float2* row = &s_in[bsel][r][j0];
            float st = 0.f, sp = 0.f, stp = 0.f;
#pragma unroll
            for (int k = 0; k < 9; ++k) {
                const float2 v = row[k];
                st += v.x; sp += v.y; stp = fmaf(v.x, v.y, stp);
            }
            s_w01[r][j0] = make_float2(st, sp);
            s_w2 [r][j0] = stp;
#pragma unroll
            for (int q = 1; q < 4; ++q) {
                const float2 va = row[8 + q];
                const float2 vs = row[q - 1];
                st  += va.x - vs.x;
                sp  += va.y - vs.y;
                stp += va.x * va.y - vs.x * vs.y;
                s_w01[r][j0 + q] = make_float2(st, sp);
                s_w2 [r][j0 + q] = stp;
            }
        }
    };

    const int ty = tid >> 5;          // 0..15 -> two h rows each
    const int tx = tid & 31;
    const int rb = ty << 1;           // first output row within tile

    // H-stage: rows rb..rb+8 -> output A ; shift one row -> output B
    auto h_stage = [&](float& a0, float& a1, float& a2,
                       float& b0, float& b1, float& b2) {
        const float2 v0 = s_w01[rb][tx];
        const float  w0v = s_w2[rb][tx];
        a0 = v0.x; a1 = v0.y; a2 = w0v;
#pragma unroll
        for (int k = 1; k < 9; ++k) {
            const float2 v = s_w01[rb + k][tx];
            a0 += v.x; a1 += v.y; a2 += s_w2[rb + k][tx];
        }
        const float2 v9 = s_w01[rb + 9][tx];
        const float  w9v = s_w2[rb + 9][tx];
        b0 = a0 - v0.x + v9.x;
        b1 = a1 - v0.y + v9.y;
        b2 = a2 - w0v + w9v;
    };

    // ---- D-dimension ring state (8 deep, 3 fields, 2 outputs/thread) ----
    float r0a[8], r1a[8], r2a[8], r0b[8], r1b[8], r2b[8];
#pragma unroll
    for (int i = 0; i < 8; ++i) {
        r0a[i] = r1a[i] = r2a[i] = 0.f;
        r0b[i] = r1b[i] = r2b[i] = 0.f;
    }
    float s0a = 0.f, s1a = 0.f, s2a = 0.f;
    float s0b = 0.f, s1b = 0.f, s2b = 0.f;

    // ---- prologue: slice d0-4 into buffer 0 ----
    int buf = 0;
    load_slice(d0 - 4);
    store_slice(0);
    __syncthreads();

    // ---- warmup: ingest slices d0-4 .. d0+3 into the ring ----
#pragma unroll
    for (int i = 0; i < 8; ++i) {
        load_slice(d0 - 3 + i);        // prefetch next
        w_stage(buf);
        store_slice(buf ^ 1);
        __syncthreads();
        float a0, a1, a2, b0, b1, b2;
        h_stage(a0, a1, a2, b0, b1, b2);
        r0a[i] = a0; r1a[i] = a1; r2a[i] = a2;
        r0b[i] = b0; r1b[i] = b1; r2b[i] = b2;
        s0a += a0; s1a += a1; s2a += a2;
        s0b += b0; s1b += b1; s2b += b2;
        __syncthreads();
        buf ^= 1;
    }

    // ---- main loop over output d = d0 .. d0+47 ----
    const int ob = b * VOL + (h0 + rb) * WW + w0 + tx;
    for (int s8 = 0; s8 < DCHUNK / 8; ++s8) {
#pragma unroll
        for (int ph = 0; ph < 8; ++ph) {
            const int step = s8 * 8 + ph;
            load_slice(d0 + 5 + step);  // prefetch next new slice
            w_stage(buf);               // current new slice = d0+4+step
            store_slice(buf ^ 1);
            __syncthreads();
            float a0, a1, a2, b0, b1, b2;
            h_stage(a0, a1, a2, b0, b1, b2);
            s0a += a0; s1a += a1; s2a += a2;
            s0b += b0; s1b += b1; s2b += b2;

            const float ca = s2a - s1a * s0a * INV_VOL;
            const float cb = s2b - s1b * s0b * INV_VOL;
            const int o = ob + (d0 + step) * PLANE;
            out[o]      = fmaf(ca, ca, EPS);
            out[o + WW] = fmaf(cb, cb, EPS);

            s0a -= r0a[ph]; r0a[ph] = a0;
            s1a -= r1a[ph]; r1a[ph] = a1;
            s2a -= r2a[ph]; r2a[ph] = a2;
            s0b -= r0b[ph]; r0b[ph] = b0;
            s1b -= r1b[ph]; r1b[ph] = b1;
            s2b -= r2b[ph]; r2b[ph] = b2;
            __syncthreads();
            buf ^= 1;
        }
    }
}

extern "C" void kernel_launch(void* const* d_in, const int* in_sizes, int n_in,
                              void* d_out, int out_size) {
    const float* y_true = (const float*)d_in[0];
    const float* y_pred = (const float*)d_in[1];
    float* out = (float*)d_out;

    // grid: 6 w-tiles x 6 h-tiles x 4 d-chunks x 2 batches = 288 blocks
    lncc_fused_kernel<<<288, NT>>>(y_true, y_pred, out);
}